// round 15
// baseline (speedup 1.0000x reference)
#include <cuda_runtime.h>
#include <cuda_fp16.h>
#include <cstdint>

#define D      256
#define BOOK   8192
#define NTOT   16384
#define HW     1024
#define MT     128              // queries per CTA
#define NT     128              // codes per chunk
#define SLICES 2                // k-slices per chunk (K=256, KS=128)
#define CHUNKS (BOOK / NT)      // 64
#define GTOT   (CHUNKS * SLICES) // 128
#define CAP    128              // candidate capacity per query
#define MARGIN 1.0f

#define A_BYTES (8 * 16 * 32 * 16)            // 65536: [mt(8)][pkt(16)][lane(32)][16B]
#define B_BYTES (NT * 256)                    // 32768 per buffer (128 rows x 256B)
#define STAGES  3
#define DYN_SMEM (A_BYTES + STAGES * B_BYTES) // 163840

__device__ __half g_ecat[BOOK][D];     // e1 (fp16 leading plane)
__device__ __half g_zcat[NTOT][D];     // z1
__device__ float  g_zrow[NTOT][D];     // exact fp32 z rows (phase 2)
__device__ float  g_enorm[BOOK];
__device__ int    g_cand[NTOT][CAP];
__device__ int    g_cnt[NTOT];

// ---------------- prep: codebook fp16 plane + norms + cnt zero ----------------
__global__ void __launch_bounds__(64) eprep_kernel(const float* __restrict__ cb) {
    int c = blockIdx.x, t = threadIdx.x;
    int gi = blockIdx.x * 64 + t;
    if (gi < NTOT) g_cnt[gi] = 0;
    float4 v = reinterpret_cast<const float4*>(cb + (size_t)c * D)[t];
    float f[4] = {v.x, v.y, v.z, v.w};
    unsigned short h[4];
#pragma unroll
    for (int i = 0; i < 4; i++) h[i] = __half_as_ushort(__float2half_rn(f[i]));
    uint2 w;
    w.x = (uint32_t)h[0] | ((uint32_t)h[1] << 16);
    w.y = (uint32_t)h[2] | ((uint32_t)h[3] << 16);
    reinterpret_cast<uint2*>(&g_ecat[c][0])[t] = w;

    float s = v.x * v.x + v.y * v.y + v.z * v.z + v.w * v.w;
#pragma unroll
    for (int o = 16; o > 0; o >>= 1) s += __shfl_down_sync(0xffffffffu, s, o);
    __shared__ float sh[2];
    if ((t & 31) == 0) sh[t >> 5] = s;
    __syncthreads();
    if (t == 0) g_enorm[c] = sh[0] + sh[1];
}

// ---------------- prep: z NCHW -> rows (fp16 plane + fp32 copy) ----------------
__global__ void __launch_bounds__(256) zprep_kernel(const float* __restrict__ ze) {
    __shared__ float zt[D][33];
    int b = blockIdx.x, hw0 = blockIdx.y * 32;
    int tid = threadIdx.x, w = tid >> 5, l = tid & 31;
    for (int k = w; k < D; k += 8)
        zt[k][l] = ze[((size_t)b * D + k) * HW + hw0 + l];
    __syncthreads();
    int r = tid >> 3, seg = tid & 7;
    int n = b * HW + hw0 + r;
#pragma unroll
    for (int i = 0; i < 32; i++) {
        int k = seg * 32 + i;
        float f = zt[k][r];
        g_zrow[n][k] = f;
        g_zcat[n][k] = __float2half_rn(f);
    }
}

// ---------------- phase 1: 1-pass fp16 GEMM + candidate filter ----------------
__device__ __forceinline__ void mma16816(float d[4], uint32_t a0, uint32_t a1,
                                         uint32_t a2, uint32_t a3,
                                         uint32_t b0, uint32_t b1) {
    asm volatile(
        "mma.sync.aligned.m16n8k16.row.col.f32.f16.f16.f32 "
        "{%0,%1,%2,%3}, {%4,%5,%6,%7}, {%8,%9}, {%0,%1,%2,%3};"
        : "+f"(d[0]), "+f"(d[1]), "+f"(d[2]), "+f"(d[3])
        : "r"(a0), "r"(a1), "r"(a2), "r"(a3), "r"(b0), "r"(b1));
}

__device__ __forceinline__ void ldmatrix_x4(uint32_t& r0, uint32_t& r1,
                                            uint32_t& r2, uint32_t& r3,
                                            uint32_t addr) {
    asm volatile("ldmatrix.sync.aligned.m8n8.x4.shared.b16 {%0,%1,%2,%3}, [%4];"
                 : "=r"(r0), "=r"(r1), "=r"(r2), "=r"(r3) : "r"(addr));
}

__device__ __forceinline__ void lds128(uint32_t& r0, uint32_t& r1,
                                       uint32_t& r2, uint32_t& r3,
                                       uint32_t addr) {
    asm volatile("ld.shared.v4.b32 {%0,%1,%2,%3}, [%4];"
                 : "=r"(r0), "=r"(r1), "=r"(r2), "=r"(r3) : "r"(addr));
}

__device__ __forceinline__ void cp16(void* dst, const void* src) {
    uint32_t d;
    asm("{ .reg .u64 t; cvta.to.shared.u64 t, %1; cvt.u32.u64 %0, t; }" : "=r"(d) : "l"(dst));
    asm volatile("cp.async.cg.shared.global [%0], [%1], 16;" :: "r"(d), "l"(src));
}
#define CP_COMMIT() asm volatile("cp.async.commit_group;" ::: "memory")
#define CP_WAIT(n)  asm volatile("cp.async.wait_group %0;" :: "n"(n) : "memory")

// B swizzled byte address: row n (256B), kb = byte offset in row (0..255)
__device__ __forceinline__ uint32_t b_addr(int n, int kb) {
    return (uint32_t)(n * 256 + (kb & 0x8F) + ((((kb >> 4) & 7) ^ (n & 7)) << 4));
}

__device__ __forceinline__ uint32_t smem_u32(const void* p) {
    uint32_t a;
    asm("{ .reg .u64 t; cvta.to.shared.u64 t, %1; cvt.u32.u64 %0, t; }" : "=r"(a) : "l"(p));
    return a;
}

__device__ __forceinline__ void cand_append(int q, int c) {
    int pos = atomicAdd(&g_cnt[q], 1);
    if (pos < CAP) g_cand[q][pos] = c;
}

extern __shared__ char dsm[];

__global__ void __launch_bounds__(256, 1) vq_phase1(int dummy)
{
    char* As = dsm;                      // fragment-layout A (z1 plane)
    char* Bs = dsm + A_BYTES;            // three 32KB B slice buffers

    const int tid = threadIdx.x;
    const int lane = tid & 31, w = tid >> 5;
    const int wm = w & 3, wn = w >> 2;   // 4 m-groups x 2 n-halves
    const int n0 = blockIdx.x * MT;
    const uint32_t Bs_u32 = smem_u32(Bs);

    // ldmatrix per-lane constants
    const int lm   = lane >> 3;
    const int row8 = lane & 7;
    const uint32_t lane_nbase = (uint32_t)((wn * 64 + ((lm >> 1) << 3) + row8) * 256);
    const uint32_t xor7  = (uint32_t)(row8 << 4);
    const uint32_t klane = (uint32_t)((lm & 1) << 4);

    const uint32_t As_u32 = smem_u32(As);
    const uint32_t a_base0 = As_u32 + (uint32_t)((((wm * 2 + 0) * 16) * 32 + lane) * 16);
    const uint32_t a_base1 = As_u32 + (uint32_t)((((wm * 2 + 1) * 16) * 32 + lane) * 16);

    // ---- build A fragments: A_frag[mt(8)][pkt(16)][lane(32)][4xb32]
    for (int i = tid; i < 8 * 16 * 32; i += 256) {
        int la = i & 31, pkt = (i >> 5) & 15, mt = (i >> 5) >> 4;
        int q  = n0 + mt * 16 + (la >> 2);
        int k0 = pkt * 16 + 2 * (la & 3);
        const char* zr = (const char*)&g_zcat[q][0];
        uint4 v;
        v.x = *(const uint32_t*)(zr + 2 * k0);
        v.y = *(const uint32_t*)(zr + 2 * k0 + 2 * 8 * D);          // row q+8
        v.z = *(const uint32_t*)(zr + 2 * (k0 + 8));
        v.w = *(const uint32_t*)(zr + 2 * (k0 + 8) + 2 * 8 * D);
        *reinterpret_cast<uint4*>(As + (size_t)i * 16) = v;
    }

    float acc[2][8][4];
    float bestv[4];
#pragma unroll
    for (int i = 0; i < 4; i++) bestv[i] = 3.0e38f;

    // ---- prologue: preload slices g=0 and g=1 into stages 0,1
#pragma unroll
    for (int pg = 0; pg < 2; pg++) {
        char* bd = Bs + pg * B_BYTES;
        const int ks = pg * 128;
#pragma unroll
        for (int j = 0; j < 8; j++) {
            int unit = tid + j * 256;
            int n = unit >> 4, u = unit & 15;
            cp16(bd + b_addr(n, u * 16), &g_ecat[n][ks + u * 8]);
        }
        CP_COMMIT();
    }

    int buf = 0, pbuf = 2;

    for (int g = 0; g < GTOT; g++) {
        const int chunk = g >> 1;
        const int s = g & 1;

        CP_WAIT(1);                      // group g complete
        __syncthreads();                 // g visible to all; all done with g-1

        if (g + 2 < GTOT) {              // prefetch g+2 into freed stage
            const int gn = g + 2;
            char* bd = Bs + pbuf * B_BYTES;
            const int c0n = (gn >> 1) * NT, ksn = (gn & 1) * 128;
#pragma unroll
            for (int j = 0; j < 8; j++) {
                int unit = tid + j * 256;
                int n = unit >> 4, u = unit & 15;
                cp16(bd + b_addr(n, u * 16), &g_ecat[c0n + n][ksn + u * 8]);
            }
        }
        CP_COMMIT();

        if (s == 0) {
#pragma unroll
            for (int mt = 0; mt < 2; mt++)
#pragma unroll
                for (int nt = 0; nt < 8; nt++)
#pragma unroll
                    for (int e = 0; e < 4; e++) acc[mt][nt][e] = 0.f;
        }

        const uint32_t bbase = Bs_u32 + (uint32_t)buf * B_BYTES + lane_nbase;
        const uint32_t a_off = (uint32_t)(s * 8) * 512u;   // pkt stride 512B

#pragma unroll
        for (int ktl = 0; ktl < 8; ktl++) {
            const uint32_t a_k = a_off + (uint32_t)ktl * 512u;
            uint32_t A0[4], A1[4];
            lds128(A0[0], A0[1], A0[2], A0[3], a_base0 + a_k);
            lds128(A1[0], A1[1], A1[2], A1[3], a_base1 + a_k);
            const uint32_t kb = (uint32_t)(ktl * 32) + klane;
            const uint32_t off = (kb & 0x80u) | ((kb & 0x70u) ^ xor7);
#pragma unroll
            for (int ntp = 0; ntp < 4; ntp++) {
                uint32_t b0, b1, b2, b3;
                ldmatrix_x4(b0, b1, b2, b3, bbase + (uint32_t)(ntp * 4096) + off);
                mma16816(acc[0][2 * ntp],     A0[0], A0[1], A0[2], A0[3], b0, b1);
                mma16816(acc[1][2 * ntp],     A1[0], A1[1], A1[2], A1[3], b0, b1);
                mma16816(acc[0][2 * ntp + 1], A0[0], A0[1], A0[2], A0[3], b2, b3);
                mma16816(acc[1][2 * ntp + 1], A1[0], A1[1], A1[2], A1[3], b2, b3);
            }
        }

        if (s == SLICES - 1) {
            const int c0 = chunk * NT + wn * 64 + 2 * (lane & 3);
            // pass 1: update running per-row minima with all 32 scores
#pragma unroll
            for (int mt = 0; mt < 2; mt++)
#pragma unroll
                for (int nt = 0; nt < 8; nt++) {
                    int cb0 = c0 + nt * 8;
                    float en0 = __ldg(&g_enorm[cb0]);
                    float en1 = __ldg(&g_enorm[cb0 + 1]);
                    float s0 = fmaf(-2.0f, acc[mt][nt][0], en0);
                    float s1 = fmaf(-2.0f, acc[mt][nt][1], en1);
                    float s2 = fmaf(-2.0f, acc[mt][nt][2], en0);
                    float s3 = fmaf(-2.0f, acc[mt][nt][3], en1);
                    bestv[mt * 2]     = fminf(bestv[mt * 2],     fminf(s0, s1));
                    bestv[mt * 2 + 1] = fminf(bestv[mt * 2 + 1], fminf(s2, s3));
                }
            // pass 2: append candidates within MARGIN of (updated) running min.
            // Running min >= final min, so this collects a superset; the true
            // argmin is always appended.
#pragma unroll
            for (int mt = 0; mt < 2; mt++) {
                const int rlo = n0 + wm * 32 + mt * 16 + (lane >> 2);
                const int rhi = rlo + 8;
                const float tlo = bestv[mt * 2]     + MARGIN;
                const float thi = bestv[mt * 2 + 1] + MARGIN;
#pragma unroll
                for (int nt = 0; nt < 8; nt++) {
                    int cb0 = c0 + nt * 8;
                    float en0 = __ldg(&g_enorm[cb0]);
                    float en1 = __ldg(&g_enorm[cb0 + 1]);
                    float s0 = fmaf(-2.0f, acc[mt][nt][0], en0);
                    float s1 = fmaf(-2.0f, acc[mt][nt][1], en1);
                    float s2 = fmaf(-2.0f, acc[mt][nt][2], en0);
                    float s3 = fmaf(-2.0f, acc[mt][nt][3], en1);
                    if (s0 < tlo) cand_append(rlo, cb0);
                    if (s1 < tlo) cand_append(rlo, cb0 + 1);
                    if (s2 < thi) cand_append(rhi, cb0);
                    if (s3 < thi) cand_append(rhi, cb0 + 1);
                }
            }
        }

        buf  = (buf  == STAGES - 1) ? 0 : buf + 1;
        pbuf = (pbuf == STAGES - 1) ? 0 : pbuf + 1;
    }
}

// ---------------- phase 2: exact double-precision rescore of candidates ----------------
__global__ void __launch_bounds__(128) vq_phase2(
    const float* __restrict__ cb, float* __restrict__ out, int Nq, int write_idx)
{
    const int q = blockIdx.x * 4 + (threadIdx.x >> 5);
    const int lane = threadIdx.x & 31;

    const float4* zr4 = reinterpret_cast<const float4*>(&g_zrow[q][0]);
    float4 z0 = zr4[2 * lane], z1 = zr4[2 * lane + 1];

    int cnt = g_cnt[q];
    bool full = (cnt > CAP);
    int m = full ? BOOK : cnt;

    double best = 1.0e300;
    int    bidx = BOOK;

    for (int i = 0; i < m; i++) {
        int c = full ? i : g_cand[q][i];
        const float4* er4 = reinterpret_cast<const float4*>(cb + (size_t)c * D);
        float4 e0 = er4[2 * lane], e1 = er4[2 * lane + 1];
        // sum_k e_k*(e_k - 2 z_k)  ==  ||e||^2 - 2 z.e   (drop ||z||^2)
        double a = 0.0;
        a += (double)e0.x * ((double)e0.x - 2.0 * (double)z0.x);
        a += (double)e0.y * ((double)e0.y - 2.0 * (double)z0.y);
        a += (double)e0.z * ((double)e0.z - 2.0 * (double)z0.z);
        a += (double)e0.w * ((double)e0.w - 2.0 * (double)z0.w);
        a += (double)e1.x * ((double)e1.x - 2.0 * (double)z1.x);
        a += (double)e1.y * ((double)e1.y - 2.0 * (double)z1.y);
        a += (double)e1.z * ((double)e1.z - 2.0 * (double)z1.z);
        a += (double)e1.w * ((double)e1.w - 2.0 * (double)z1.w);
#pragma unroll
        for (int o = 16; o > 0; o >>= 1)
            a += __shfl_down_sync(0xffffffffu, a, o);
        if (lane == 0) {
            if (a < best || (a == best && c < bidx)) { best = a; bidx = c; }
        }
    }
    bidx = __shfl_sync(0xffffffffu, bidx, 0);

    if (write_idx && lane == 0) out[(size_t)Nq * D + q] = (float)bidx;

    // gather z_q row (coalesced)
    const float4* src = reinterpret_cast<const float4*>(cb + (size_t)bidx * D);
    float4* dst = reinterpret_cast<float4*>(out + (size_t)q * D);
    dst[lane]      = src[lane];
    dst[lane + 32] = src[lane + 32];
}

extern "C" void kernel_launch(void* const* d_in, const int* in_sizes, int n_in,
                              void* d_out, int out_size) {
    const float* ze = (const float*)d_in[0];
    const float* cb = (const float*)d_in[1];
    float* out = (float*)d_out;

    int Nq = in_sizes[0] / D;                 // 16384
    int nb = Nq / HW;                         // 16
    int write_idx = (out_size >= Nq * D + Nq) ? 1 : 0;

    cudaFuncSetAttribute(vq_phase1, cudaFuncAttributeMaxDynamicSharedMemorySize, DYN_SMEM);

    eprep_kernel<<<BOOK, 64>>>(cb);
    zprep_kernel<<<dim3(nb, 32), 256>>>(ze);
    vq_phase1<<<Nq / MT, 256, DYN_SMEM>>>(0);
    vq_phase2<<<Nq / 4, 128>>>(cb, out, Nq, write_idx);
}

// round 16
// speedup vs baseline: 5.7208x; 5.7208x over previous
#include <cuda_runtime.h>
#include <cuda_fp16.h>
#include <cstdint>

#define D      256
#define BOOK   8192
#define NTOT   16384
#define HW     1024
#define MT     128              // queries per CTA
#define NT     128              // codes per chunk
#define SLICES 2                // k-slices per chunk (K=256, KS=128)
#define CHUNKS (BOOK / NT)      // 64
#define GTOT   (CHUNKS * SLICES) // 128
#define MARGIN 3.0f

#define A_BYTES (8 * 16 * 32 * 16)            // 65536: [mt(8)][pkt(16)][lane(32)][16B]
#define B_BYTES (NT * 256)                    // 32768 per buffer (128 rows x 256B)
#define STAGES  3
#define DYN_SMEM (A_BYTES + STAGES * B_BYTES) // 163840

__device__ __half g_ecat[BOOK][D];     // e fp16 plane
__device__ __half g_zcat[NTOT][D];     // z fp16 plane
__device__ float  g_zrow[NTOT][D];     // exact fp32 z rows
__device__ float  g_enorm[BOOK];
__device__ float  g_cmin[NTOT][512];   // per-(query, chunk*8+slot) approx min of 16 codes

// ---------------- prep: codebook fp16 plane + norms ----------------
__global__ void __launch_bounds__(64) eprep_kernel(const float* __restrict__ cb) {
    int c = blockIdx.x, t = threadIdx.x;
    float4 v = reinterpret_cast<const float4*>(cb + (size_t)c * D)[t];
    float f[4] = {v.x, v.y, v.z, v.w};
    unsigned short h[4];
#pragma unroll
    for (int i = 0; i < 4; i++) h[i] = __half_as_ushort(__float2half_rn(f[i]));
    uint2 w;
    w.x = (uint32_t)h[0] | ((uint32_t)h[1] << 16);
    w.y = (uint32_t)h[2] | ((uint32_t)h[3] << 16);
    reinterpret_cast<uint2*>(&g_ecat[c][0])[t] = w;

    float s = v.x * v.x + v.y * v.y + v.z * v.z + v.w * v.w;
#pragma unroll
    for (int o = 16; o > 0; o >>= 1) s += __shfl_down_sync(0xffffffffu, s, o);
    __shared__ float sh[2];
    if ((t & 31) == 0) sh[t >> 5] = s;
    __syncthreads();
    if (t == 0) g_enorm[c] = sh[0] + sh[1];
}

// ---------------- prep: z NCHW -> rows (fp16 plane + fp32 copy) ----------------
__global__ void __launch_bounds__(256) zprep_kernel(const float* __restrict__ ze) {
    __shared__ float zt[D][33];
    int b = blockIdx.x, hw0 = blockIdx.y * 32;
    int tid = threadIdx.x, w = tid >> 5, l = tid & 31;
    for (int k = w; k < D; k += 8)
        zt[k][l] = ze[((size_t)b * D + k) * HW + hw0 + l];
    __syncthreads();
    int r = tid >> 3, seg = tid & 7;
    int n = b * HW + hw0 + r;
#pragma unroll
    for (int i = 0; i < 32; i++) {
        int k = seg * 32 + i;
        float f = zt[k][r];
        g_zrow[n][k] = f;
        g_zcat[n][k] = __float2half_rn(f);
    }
}

// ---------------- phase 1: 1-pass fp16 GEMM + per-slot chunk minima ----------------
__device__ __forceinline__ void mma16816(float d[4], uint32_t a0, uint32_t a1,
                                         uint32_t a2, uint32_t a3,
                                         uint32_t b0, uint32_t b1) {
    asm volatile(
        "mma.sync.aligned.m16n8k16.row.col.f32.f16.f16.f32 "
        "{%0,%1,%2,%3}, {%4,%5,%6,%7}, {%8,%9}, {%0,%1,%2,%3};"
        : "+f"(d[0]), "+f"(d[1]), "+f"(d[2]), "+f"(d[3])
        : "r"(a0), "r"(a1), "r"(a2), "r"(a3), "r"(b0), "r"(b1));
}

__device__ __forceinline__ void ldmatrix_x4(uint32_t& r0, uint32_t& r1,
                                            uint32_t& r2, uint32_t& r3,
                                            uint32_t addr) {
    asm volatile("ldmatrix.sync.aligned.m8n8.x4.shared.b16 {%0,%1,%2,%3}, [%4];"
                 : "=r"(r0), "=r"(r1), "=r"(r2), "=r"(r3) : "r"(addr));
}

__device__ __forceinline__ void lds128(uint32_t& r0, uint32_t& r1,
                                       uint32_t& r2, uint32_t& r3,
                                       uint32_t addr) {
    asm volatile("ld.shared.v4.b32 {%0,%1,%2,%3}, [%4];"
                 : "=r"(r0), "=r"(r1), "=r"(r2), "=r"(r3) : "r"(addr));
}

__device__ __forceinline__ void cp16(void* dst, const void* src) {
    uint32_t d;
    asm("{ .reg .u64 t; cvta.to.shared.u64 t, %1; cvt.u32.u64 %0, t; }" : "=r"(d) : "l"(dst));
    asm volatile("cp.async.cg.shared.global [%0], [%1], 16;" :: "r"(d), "l"(src));
}
#define CP_COMMIT() asm volatile("cp.async.commit_group;" ::: "memory")
#define CP_WAIT(n)  asm volatile("cp.async.wait_group %0;" :: "n"(n) : "memory")

__device__ __forceinline__ uint32_t b_addr(int n, int kb) {
    return (uint32_t)(n * 256 + (kb & 0x8F) + ((((kb >> 4) & 7) ^ (n & 7)) << 4));
}

__device__ __forceinline__ uint32_t smem_u32(const void* p) {
    uint32_t a;
    asm("{ .reg .u64 t; cvta.to.shared.u64 t, %1; cvt.u32.u64 %0, t; }" : "=r"(a) : "l"(p));
    return a;
}

extern __shared__ char dsm[];

__global__ void __launch_bounds__(256, 1) vq_phase1(int dummy)
{
    char* As = dsm;
    char* Bs = dsm + A_BYTES;

    const int tid = threadIdx.x;
    const int lane = tid & 31, w = tid >> 5;
    const int wm = w & 3, wn = w >> 2;   // 4 m-groups x 2 n-halves
    const int n0 = blockIdx.x * MT;
    const uint32_t Bs_u32 = smem_u32(Bs);

    const int lm   = lane >> 3;
    const int row8 = lane & 7;
    const uint32_t lane_nbase = (uint32_t)((wn * 64 + ((lm >> 1) << 3) + row8) * 256);
    const uint32_t xor7  = (uint32_t)(row8 << 4);
    const uint32_t klane = (uint32_t)((lm & 1) << 4);

    const uint32_t As_u32 = smem_u32(As);
    const uint32_t a_base0 = As_u32 + (uint32_t)((((wm * 2 + 0) * 16) * 32 + lane) * 16);
    const uint32_t a_base1 = As_u32 + (uint32_t)((((wm * 2 + 1) * 16) * 32 + lane) * 16);

    // ---- build A fragments: A_frag[mt(8)][pkt(16)][lane(32)][4xb32]
    for (int i = tid; i < 8 * 16 * 32; i += 256) {
        int la = i & 31, pkt = (i >> 5) & 15, mt = (i >> 5) >> 4;
        int q  = n0 + mt * 16 + (la >> 2);
        int k0 = pkt * 16 + 2 * (la & 3);
        const char* zr = (const char*)&g_zcat[q][0];
        uint4 v;
        v.x = *(const uint32_t*)(zr + 2 * k0);
        v.y = *(const uint32_t*)(zr + 2 * k0 + 2 * 8 * D);
        v.z = *(const uint32_t*)(zr + 2 * (k0 + 8));
        v.w = *(const uint32_t*)(zr + 2 * (k0 + 8) + 2 * 8 * D);
        *reinterpret_cast<uint4*>(As + (size_t)i * 16) = v;
    }

    float acc[2][8][4];

    // ---- prologue: preload slices g=0 and g=1
#pragma unroll
    for (int pg = 0; pg < 2; pg++) {
        char* bd = Bs + pg * B_BYTES;
        const int ks = pg * 128;
#pragma unroll
        for (int j = 0; j < 8; j++) {
            int unit = tid + j * 256;
            int n = unit >> 4, u = unit & 15;
            cp16(bd + b_addr(n, u * 16), &g_ecat[n][ks + u * 8]);
        }
        CP_COMMIT();
    }

    int buf = 0, pbuf = 2;

    for (int g = 0; g < GTOT; g++) {
        const int chunk = g >> 1;
        const int s = g & 1;

        CP_WAIT(1);
        __syncthreads();

        if (g + 2 < GTOT) {
            const int gn = g + 2;
            char* bd = Bs + pbuf * B_BYTES;
            const int c0n = (gn >> 1) * NT, ksn = (gn & 1) * 128;
#pragma unroll
            for (int j = 0; j < 8; j++) {
                int unit = tid + j * 256;
                int n = unit >> 4, u = unit & 15;
                cp16(bd + b_addr(n, u * 16), &g_ecat[c0n + n][ksn + u * 8]);
            }
        }
        CP_COMMIT();

        if (s == 0) {
#pragma unroll
            for (int mt = 0; mt < 2; mt++)
#pragma unroll
                for (int nt = 0; nt < 8; nt++)
#pragma unroll
                    for (int e = 0; e < 4; e++) acc[mt][nt][e] = 0.f;
        }

        const uint32_t bbase = Bs_u32 + (uint32_t)buf * B_BYTES + lane_nbase;
        const uint32_t a_off = (uint32_t)(s * 8) * 512u;

#pragma unroll
        for (int ktl = 0; ktl < 8; ktl++) {
            const uint32_t a_k = a_off + (uint32_t)ktl * 512u;
            uint32_t A0[4], A1[4];
            lds128(A0[0], A0[1], A0[2], A0[3], a_base0 + a_k);
            lds128(A1[0], A1[1], A1[2], A1[3], a_base1 + a_k);
            const uint32_t kb = (uint32_t)(ktl * 32) + klane;
            const uint32_t off = (kb & 0x80u) | ((kb & 0x70u) ^ xor7);
#pragma unroll
            for (int ntp = 0; ntp < 4; ntp++) {
                uint32_t b0, b1, b2, b3;
                ldmatrix_x4(b0, b1, b2, b3, bbase + (uint32_t)(ntp * 4096) + off);
                mma16816(acc[0][2 * ntp],     A0[0], A0[1], A0[2], A0[3], b0, b1);
                mma16816(acc[1][2 * ntp],     A1[0], A1[1], A1[2], A1[3], b0, b1);
                mma16816(acc[0][2 * ntp + 1], A0[0], A0[1], A0[2], A0[3], b2, b3);
                mma16816(acc[1][2 * ntp + 1], A1[0], A1[1], A1[2], A1[3], b2, b3);
            }
        }

        if (s == SLICES - 1) {
            // per-slot chunk minima: each thread owns 16 scores per row
            const int c0 = chunk * NT + wn * 64 + 2 * (lane & 3);
            const int cbase = chunk * 8 + wn * 4 + (lane & 3);
#pragma unroll
            for (int mt = 0; mt < 2; mt++) {
                float mlo = 3.0e38f, mhi = 3.0e38f;
#pragma unroll
                for (int nt = 0; nt < 8; nt++) {
                    int cb0 = c0 + nt * 8;
                    float en0 = __ldg(&g_enorm[cb0]);
                    float en1 = __ldg(&g_enorm[cb0 + 1]);
                    float s0 = fmaf(-2.0f, acc[mt][nt][0], en0);
                    float s1 = fmaf(-2.0f, acc[mt][nt][1], en1);
                    float s2 = fmaf(-2.0f, acc[mt][nt][2], en0);
                    float s3 = fmaf(-2.0f, acc[mt][nt][3], en1);
                    mlo = fminf(mlo, fminf(s0, s1));
                    mhi = fminf(mhi, fminf(s2, s3));
                }
                const int rlo = n0 + wm * 32 + mt * 16 + (lane >> 2);
                g_cmin[rlo][cbase]     = mlo;
                g_cmin[rlo + 8][cbase] = mhi;
            }
        }

        buf  = (buf  == STAGES - 1) ? 0 : buf + 1;
        pbuf = (pbuf == STAGES - 1) ? 0 : pbuf + 1;
    }
}

// ---------------- phase 2: slot filter + exact fp32 rescore ----------------
__global__ void __launch_bounds__(128) vq_phase2(
    const float* __restrict__ cb, float* __restrict__ out, int Nq, int write_idx)
{
    __shared__ int s_list[4][64];
    __shared__ int s_cnt[4];

    const int wid = threadIdx.x >> 5, lane = threadIdx.x & 31;
    const int q = blockIdx.x * 4 + wid;

    if (lane == 0) s_cnt[wid] = 0;

    // z row chunk for this lane (8 dims)
    const float4* zr4 = reinterpret_cast<const float4*>(&g_zrow[q][0]);
    const float4 zz0 = zr4[lane * 2], zz1 = zr4[lane * 2 + 1];

    // 16 slot-mins per lane (covers slots lane*16 .. lane*16+15)
    const float4* cm4 = reinterpret_cast<const float4*>(&g_cmin[q][0]);
    float sm[16];
#pragma unroll
    for (int j = 0; j < 4; j++) {
        float4 v = cm4[lane * 4 + j];
        sm[4 * j + 0] = v.x; sm[4 * j + 1] = v.y;
        sm[4 * j + 2] = v.z; sm[4 * j + 3] = v.w;
    }
    float lmin = sm[0];
#pragma unroll
    for (int j = 1; j < 16; j++) lmin = fminf(lmin, sm[j]);
#pragma unroll
    for (int o = 16; o > 0; o >>= 1)
        lmin = fminf(lmin, __shfl_xor_sync(0xffffffffu, lmin, o));
    const float thr = lmin + MARGIN;
    __syncwarp();

#pragma unroll
    for (int j = 0; j < 16; j++)
        if (sm[j] < thr) {
            int p = atomicAdd(&s_cnt[wid], 1);
            if (p < 64) s_list[wid][p] = lane * 16 + j;
        }
    __syncwarp();

    int m = s_cnt[wid];
    const bool full = (m > 64);
    if (full) m = 512;

    float bestv = 3.0e38f;
    int   besti = BOOK;

    for (int i = 0; i < m; i++) {
        const int s512 = full ? i : s_list[wid][i];
        const int ch = s512 >> 3, wn = (s512 >> 2) & 1, q2 = s512 & 3;
        const int base = ch * 128 + wn * 64 + 2 * q2;
        // slot's 16 codes: base + nt*8 + e, nt 0..7, e 0..1; process 2 at a time
#pragma unroll 2
        for (int nt = 0; nt < 8; nt++) {
            const int ca = base + nt * 8, cbn = ca + 1;
            const float4* ea = reinterpret_cast<const float4*>(cb + (size_t)ca * D);
            const float4* eb = reinterpret_cast<const float4*>(cb + (size_t)cbn * D);
            float4 a0 = ea[lane * 2], a1 = ea[lane * 2 + 1];
            float4 b0 = eb[lane * 2], b1 = eb[lane * 2 + 1];
            // partial of ||e||^2 - 2 z.e over this lane's 8 dims
            float pa = a0.x * (a0.x - 2.f * zz0.x);
            pa = fmaf(a0.y, a0.y - 2.f * zz0.y, pa);
            pa = fmaf(a0.z, a0.z - 2.f * zz0.z, pa);
            pa = fmaf(a0.w, a0.w - 2.f * zz0.w, pa);
            pa = fmaf(a1.x, a1.x - 2.f * zz1.x, pa);
            pa = fmaf(a1.y, a1.y - 2.f * zz1.y, pa);
            pa = fmaf(a1.z, a1.z - 2.f * zz1.z, pa);
            pa = fmaf(a1.w, a1.w - 2.f * zz1.w, pa);
            float pb = b0.x * (b0.x - 2.f * zz0.x);
            pb = fmaf(b0.y, b0.y - 2.f * zz0.y, pb);
            pb = fmaf(b0.z, b0.z - 2.f * zz0.z, pb);
            pb = fmaf(b0.w, b0.w - 2.f * zz0.w, pb);
            pb = fmaf(b1.x, b1.x - 2.f * zz1.x, pb);
            pb = fmaf(b1.y, b1.y - 2.f * zz1.y, pb);
            pb = fmaf(b1.z, b1.z - 2.f * zz1.z, pb);
            pb = fmaf(b1.w, b1.w - 2.f * zz1.w, pb);
#pragma unroll
            for (int o = 16; o > 0; o >>= 1) {
                pa += __shfl_xor_sync(0xffffffffu, pa, o);
                pb += __shfl_xor_sync(0xffffffffu, pb, o);
            }
            // butterfly leaves full sums in all lanes -> uniform update
            if (pa < bestv || (pa == bestv && ca < besti)) { bestv = pa; besti = ca; }
            if (pb < bestv || (pb == bestv && cbn < besti)) { bestv = pb; besti = cbn; }
        }
    }

    if (write_idx && lane == 0) out[(size_t)Nq * D + q] = (float)besti;

    // gather z_q row (coalesced)
    const float4* src = reinterpret_cast<const float4*>(cb + (size_t)besti * D);
    float4* dst = reinterpret_cast<float4*>(out + (size_t)q * D);
    dst[lane]      = src[lane];
    dst[lane + 32] = src[lane + 32];
}

extern "C" void kernel_launch(void* const* d_in, const int* in_sizes, int n_in,
                              void* d_out, int out_size) {
    const float* ze = (const float*)d_in[0];
    const float* cb = (const float*)d_in[1];
    float* out = (float*)d_out;

    int Nq = in_sizes[0] / D;                 // 16384
    int nb = Nq / HW;                         // 16
    int write_idx = (out_size >= Nq * D + Nq) ? 1 : 0;

    cudaFuncSetAttribute(vq_phase1, cudaFuncAttributeMaxDynamicSharedMemorySize, DYN_SMEM);

    eprep_kernel<<<BOOK, 64>>>(cb);
    zprep_kernel<<<dim3(nb, 32), 256>>>(ze);
    vq_phase1<<<Nq / MT, 256, DYN_SMEM>>>(0);
    vq_phase2<<<Nq / 4, 128>>>(cb, out, Nq, write_idx);
}